// round 6
// baseline (speedup 1.0000x reference)
#include <cuda_runtime.h>
#include <cuda_bf16.h>
#include <cstdint>

// Problem constants
#define B_   16384
#define DIN  1024
#define D_   512
#define K_   8192
#define KP2  3072          // gemm1 packed K: [a0|a0|a1] . [b0|b1|b0]

#define MARGIN 0.045f
#define CCAP   16

// ---------------------------------------------------------------------------
// Scratch (device globals; allocations forbidden)
// ---------------------------------------------------------------------------
__device__ float g_ze[(size_t)B_ * D_];     // z_e fp32
__device__ float g_c2[K_];
__device__ float g_zz[B_];
__device__ int   g_idx[B_];
__device__ float g_gmin[B_];
__device__ int   g_cand[B_ * CCAP];
__device__ int   g_cand_cnt[B_];
__device__ float g_spill_val[B_ * CCAP];
__device__ int   g_spill_idx[B_ * CCAP];
__device__ int   g_spill_cnt[B_];
__device__ __nv_bfloat16 g_xs[(size_t)B_ * KP2];   // packed x splits
__device__ __nv_bfloat16 g_ws[(size_t)D_ * KP2];   // packed W splits
__device__ __nv_bfloat16 g_zb[(size_t)B_ * D_];    // bf16(z_e)
__device__ __nv_bfloat16 g_cbb[(size_t)K_ * D_];   // bf16(cb)

// ---------------------------------------------------------------------------
// PTX helpers (baseline PTX only: works at .target sm_100)
// ---------------------------------------------------------------------------
__device__ __forceinline__ uint32_t smem_u32(const void* p) {
    uint32_t a;
    asm("{ .reg .u64 t; cvta.to.shared.u64 t, %1; cvt.u32.u64 %0, t; }" : "=r"(a) : "l"(p));
    return a;
}
__device__ __forceinline__ void cp_async16(uint32_t saddr, const void* gaddr) {
    asm volatile("cp.async.cg.shared.global [%0], [%1], 16;" :: "r"(saddr), "l"(gaddr));
}
__device__ __forceinline__ void cp_commit() { asm volatile("cp.async.commit_group;"); }
__device__ __forceinline__ void cp_wait1()  { asm volatile("cp.async.wait_group 1;" ::: "memory"); }

__device__ __forceinline__ void ldsm_x4(uint32_t& r0, uint32_t& r1, uint32_t& r2, uint32_t& r3,
                                        uint32_t addr) {
    asm volatile("ldmatrix.sync.aligned.m8n8.x4.shared.b16 {%0,%1,%2,%3}, [%4];"
                 : "=r"(r0), "=r"(r1), "=r"(r2), "=r"(r3) : "r"(addr));
}
__device__ __forceinline__ void mma_bf16(float* c, const uint32_t* a, uint32_t b0, uint32_t b1) {
    asm volatile("mma.sync.aligned.m16n8k16.row.col.f32.bf16.bf16.f32 "
                 "{%0,%1,%2,%3}, {%4,%5,%6,%7}, {%8,%9}, {%0,%1,%2,%3};"
                 : "+f"(c[0]), "+f"(c[1]), "+f"(c[2]), "+f"(c[3])
                 : "r"(a[0]), "r"(a[1]), "r"(a[2]), "r"(a[3]), "r"(b0), "r"(b1));
}

// A-resident swizzle for 512-col bf16 rows (64 x 16B chunks per row)
#define SWA(r, c) ((r) * 1024 + ((((c) & 0x38) | (((c) & 7) ^ ((r) & 7))) << 4))

__device__ __forceinline__ void spill_push(int row, float v, int k) {
    int p = atomicAdd(&g_spill_cnt[row], 1);
    if (p < CCAP) { g_spill_val[row * CCAP + p] = v; g_spill_idx[row * CCAP + p] = k; }
}

// ---------------------------------------------------------------------------
// c2 / zz
// ---------------------------------------------------------------------------
__global__ void c2_kernel(const float* __restrict__ cb) {
    int row  = blockIdx.x * 8 + (threadIdx.x >> 5);
    int lane = threadIdx.x & 31;
    const float* p = cb + (size_t)row * D_;
    float s = 0.f;
    #pragma unroll 4
    for (int i = lane; i < D_; i += 32) { float v = p[i]; s += v * v; }
    #pragma unroll
    for (int o = 16; o; o >>= 1) s += __shfl_xor_sync(0xffffffffu, s, o);
    if (lane == 0) g_c2[row] = s;
}

__global__ void zz_kernel() {
    int row  = blockIdx.x * 8 + (threadIdx.x >> 5);
    int lane = threadIdx.x & 31;
    const float* p = g_ze + (size_t)row * D_;
    double s = 0.0;
    #pragma unroll 4
    for (int i = lane; i < D_; i += 32) { double v = (double)p[i]; s += v * v; }
    #pragma unroll
    for (int o = 16; o; o >>= 1) s += __shfl_xor_sync(0xffffffffu, s, o);
    if (lane == 0) g_zz[row] = (float)s;
}

// ---------------------------------------------------------------------------
// Pack kernels
// ---------------------------------------------------------------------------
__global__ void pack_x_kernel(const float* __restrict__ x) {
    const int row = blockIdx.x, t = threadIdx.x;
    float4 v = *reinterpret_cast<const float4*>(x + (size_t)row * DIN + t * 4);
    __nv_bfloat162 h01, h23, l01, l23;
    h01.x = __float2bfloat16_rn(v.x); h01.y = __float2bfloat16_rn(v.y);
    h23.x = __float2bfloat16_rn(v.z); h23.y = __float2bfloat16_rn(v.w);
    l01.x = __float2bfloat16_rn(v.x - __bfloat162float(h01.x));
    l01.y = __float2bfloat16_rn(v.y - __bfloat162float(h01.y));
    l23.x = __float2bfloat16_rn(v.z - __bfloat162float(h23.x));
    l23.y = __float2bfloat16_rn(v.w - __bfloat162float(h23.y));
    __nv_bfloat162* d = reinterpret_cast<__nv_bfloat162*>(g_xs + (size_t)row * KP2 + t * 4);
    d[0] = h01; d[1] = h23;
    d += 512;  d[0] = h01; d[1] = h23;
    d += 512;  d[0] = l01; d[1] = l23;
}

__global__ void pack_w_kernel(const float* __restrict__ w) {
    const int row = blockIdx.x, t = threadIdx.x;
    float4 v = *reinterpret_cast<const float4*>(w + (size_t)row * DIN + t * 4);
    __nv_bfloat162 h01, h23, l01, l23;
    h01.x = __float2bfloat16_rn(v.x); h01.y = __float2bfloat16_rn(v.y);
    h23.x = __float2bfloat16_rn(v.z); h23.y = __float2bfloat16_rn(v.w);
    l01.x = __float2bfloat16_rn(v.x - __bfloat162float(h01.x));
    l01.y = __float2bfloat16_rn(v.y - __bfloat162float(h01.y));
    l23.x = __float2bfloat16_rn(v.z - __bfloat162float(h23.x));
    l23.y = __float2bfloat16_rn(v.w - __bfloat162float(h23.y));
    __nv_bfloat162* d = reinterpret_cast<__nv_bfloat162*>(g_ws + (size_t)row * KP2 + t * 4);
    d[0] = h01; d[1] = h23;
    d += 512;  d[0] = l01; d[1] = l23;
    d += 512;  d[0] = h01; d[1] = h23;
}

__global__ void pack_cb_kernel(const float* __restrict__ cb) {
    size_t i = ((size_t)blockIdx.x * 256 + threadIdx.x) * 2;
    float2 v = *reinterpret_cast<const float2*>(cb + i);
    __nv_bfloat162 h; h.x = __float2bfloat16_rn(v.x); h.y = __float2bfloat16_rn(v.y);
    *reinterpret_cast<__nv_bfloat162*>(g_cbb + i) = h;
}

__global__ void pack_zb_kernel() {
    size_t i = ((size_t)blockIdx.x * 256 + threadIdx.x) * 2;
    float2 v = *reinterpret_cast<const float2*>(g_ze + i);
    __nv_bfloat162 h; h.x = __float2bfloat16_rn(v.x); h.y = __float2bfloat16_rn(v.y);
    *reinterpret_cast<__nv_bfloat162*>(g_zb + i) = h;
}

// ---------------------------------------------------------------------------
// GEMM1 via mma.sync: z_e = x @ W^T with packed 3-split (K''=3072).
// ---------------------------------------------------------------------------
#define NS1    3
#define BLKK   64
#define STAGEB 16384
#define SM1_B  (NS1 * STAGEB)
#define SM1TOT (2 * NS1 * STAGEB)   // 96KB

__global__ __launch_bounds__(256, 1) void gemm1_mma_kernel() {
    extern __shared__ char sm[];
    const uint32_t sbase = smem_u32(sm);
    const int tid  = threadIdx.x;
    const int lane = tid & 31;
    const int wid  = tid >> 5;
    const int warp_m = wid & 1;
    const int warp_n = wid >> 1;
    const int row0 = blockIdx.y * 128;
    const int col0 = blockIdx.x * 128;
    const int NKIT = KP2 / BLKK;      // 48

    const __nv_bfloat16* gA = g_xs + (size_t)row0 * KP2;
    const __nv_bfloat16* gB = g_ws + (size_t)col0 * KP2;

    float acc[4][4][4];
    #pragma unroll
    for (int mf = 0; mf < 4; mf++)
        #pragma unroll
        for (int nf = 0; nf < 4; nf++)
            #pragma unroll
            for (int q = 0; q < 4; q++) acc[mf][nf][q] = 0.f;

    #define G1_ISSUE(stg, kit) do {                                                \
        const uint32_t As_ = sbase + (stg) * STAGEB;                               \
        const uint32_t Bs_ = sbase + SM1_B + (stg) * STAGEB;                       \
        const int koff_ = (kit) * BLKK;                                            \
        _Pragma("unroll")                                                          \
        for (int i_ = 0; i_ < 4; i_++) {                                           \
            int id_ = tid + i_ * 256;                                              \
            int r_  = id_ >> 3;                                                    \
            int c_  = id_ & 7;                                                     \
            int cp_ = c_ ^ (r_ & 7);                                               \
            cp_async16(As_ + r_ * 128 + cp_ * 16, gA + (size_t)r_ * KP2 + koff_ + c_ * 8); \
            cp_async16(Bs_ + r_ * 128 + cp_ * 16, gB + (size_t)r_ * KP2 + koff_ + c_ * 8); \
        }                                                                          \
    } while (0)

    G1_ISSUE(0, 0); cp_commit();
    G1_ISSUE(1, 1); cp_commit();

    const int g = lane >> 3;
    const int r8 = lane & 7;

    for (int kit = 0; kit < NKIT; kit++) {
        cp_wait1();
        __syncthreads();
        if (kit + 2 < NKIT) G1_ISSUE((kit + 2) % NS1, kit + 2);
        cp_commit();

        const int stg = kit % NS1;
        const uint32_t Abase = sbase + stg * STAGEB;
        const uint32_t Bbase = sbase + SM1_B + stg * STAGEB;

        #pragma unroll
        for (int ks = 0; ks < 4; ks++) {
            uint32_t afr[4][4];
            #pragma unroll
            for (int mf = 0; mf < 4; mf++) {
                int rr = warp_m * 64 + mf * 16 + ((g & 1) << 3) + r8;
                int ch = 2 * ks + (g >> 1);
                ldsm_x4(afr[mf][0], afr[mf][1], afr[mf][2], afr[mf][3],
                        Abase + rr * 128 + ((ch ^ (rr & 7)) << 4));
            }
            uint32_t bfr[2][4];
            #pragma unroll
            for (int nf2 = 0; nf2 < 2; nf2++) {
                int rr = warp_n * 32 + nf2 * 16 + ((g >> 1) << 3) + r8;
                int ch = 2 * ks + (g & 1);
                ldsm_x4(bfr[nf2][0], bfr[nf2][1], bfr[nf2][2], bfr[nf2][3],
                        Bbase + rr * 128 + ((ch ^ (rr & 7)) << 4));
            }
            #pragma unroll
            for (int mf = 0; mf < 4; mf++)
                #pragma unroll
                for (int nf = 0; nf < 4; nf++)
                    mma_bf16(acc[mf][nf], afr[mf],
                             bfr[nf >> 1][(nf & 1) * 2], bfr[nf >> 1][(nf & 1) * 2 + 1]);
        }
    }
    #undef G1_ISSUE

    #pragma unroll
    for (int mf = 0; mf < 4; mf++)
        #pragma unroll
        for (int h = 0; h < 2; h++) {
            const int row = row0 + warp_m * 64 + mf * 16 + h * 8 + (lane >> 2);
            #pragma unroll
            for (int nf = 0; nf < 4; nf++) {
                const int col = col0 + warp_n * 32 + nf * 8 + (lane & 3) * 2;
                float2 o; o.x = acc[mf][nf][h * 2]; o.y = acc[mf][nf][h * 2 + 1];
                *reinterpret_cast<float2*>(g_ze + (size_t)row * D_ + col) = o;
            }
        }
}

// ---------------------------------------------------------------------------
// Phase 1 (fused): single bf16 pass over ALL codes, per-owner top-2 + spill.
// Block = 128 rows; A resident (128KB swizzled); B streamed, 3-stage ring.
// grid = 128. Ends with per-row 32-value reduce -> gmin + candidate list.
// ---------------------------------------------------------------------------
#define P1_SM_A  0
#define P1_SM_B  131072
#define P1_SMTOT (131072 + 3 * STAGEB)   // 180224

__global__ __launch_bounds__(256, 1) void phase1_kernel() {
    extern __shared__ char sm[];
    const uint32_t sbase = smem_u32(sm);
    const int tid  = threadIdx.x;
    const int lane = tid & 31;
    const int wid  = tid >> 5;
    const int warp_m = wid & 1;
    const int warp_n = wid >> 1;
    const int row0 = blockIdx.x * 128;

    // zero spill counters for our rows (graph-replay safe; block owns rows)
    if (tid < 128) g_spill_cnt[row0 + tid] = 0;

    // resident A: 128 rows x 64 chunks(16B)
    {
        const __nv_bfloat16* gA = g_zb + (size_t)row0 * D_;
        #pragma unroll
        for (int i = 0; i < 32; i++) {
            int idx = tid + i * 256;
            int r   = idx >> 6;
            int c16 = idx & 63;
            cp_async16(sbase + P1_SM_A + SWA(r, c16), gA + (size_t)r * D_ + c16 * 8);
        }
    }
    cp_commit();

    #define P1_ISSUE(stg, u) do {                                                  \
        const uint32_t Bs_ = sbase + P1_SM_B + (stg) * STAGEB;                     \
        const int nt_ = (u) >> 3, kit_ = (u) & 7;                                  \
        const __nv_bfloat16* gB_ = g_cbb + (size_t)(nt_ * 128) * D_;               \
        _Pragma("unroll")                                                          \
        for (int i_ = 0; i_ < 4; i_++) {                                           \
            int id_ = tid + i_ * 256;                                              \
            int r_  = id_ >> 3;                                                    \
            int c_  = id_ & 7;                                                     \
            cp_async16(Bs_ + r_ * 128 + ((c_ ^ (r_ & 7)) << 4),                    \
                       gB_ + (size_t)r_ * D_ + kit_ * BLKK + c_ * 8);              \
        }                                                                          \
    } while (0)

    P1_ISSUE(0, 0); cp_commit();
    P1_ISSUE(1, 1); cp_commit();

    const int g = lane >> 3;
    const int r8 = lane & 7;

    // per-owner top-2 state for 8 row-slots
    float tv1[8], tv2[8];
    int   ti1[8], ti2[8];
    int   rowg[8];
    #pragma unroll
    for (int mf = 0; mf < 4; mf++)
        #pragma unroll
        for (int h = 0; h < 2; h++) {
            const int ridx = mf * 2 + h;
            tv1[ridx] = 3.4e38f; tv2[ridx] = 3.4e38f;
            ti1[ridx] = 0x7fffffff; ti2[ridx] = 0x7fffffff;
            rowg[ridx] = row0 + warp_m * 64 + mf * 16 + h * 8 + (lane >> 2);
        }

    #define TOP2_UPD(v, k, ridx) do {                                              \
        if ((v) < tv2[ridx]) {                                                     \
            float ev_ = tv2[ridx]; int ei_ = ti2[ridx];                            \
            if ((v) < tv1[ridx]) {                                                 \
                tv2[ridx] = tv1[ridx]; ti2[ridx] = ti1[ridx];                      \
                tv1[ridx] = (v); ti1[ridx] = (k);                                  \
                if (ev_ < (v) + MARGIN) spill_push(rowg[ridx], ev_, ei_);          \
            } else {                                                               \
                tv2[ridx] = (v); ti2[ridx] = (k);                                  \
                if (ev_ < tv1[ridx] + MARGIN) spill_push(rowg[ridx], ev_, ei_);    \
            }                                                                      \
        } else if ((v) < tv1[ridx] + MARGIN) {                                     \
            spill_push(rowg[ridx], (v), (k));                                      \
        }                                                                          \
    } while (0)

    float acc[4][4][4];

    for (int u = 0; u < 512; u++) {
        const int nt = u >> 3, kit = u & 7;
        cp_wait1();
        __syncthreads();
        if (u + 2 < 512) P1_ISSUE((u + 2) % 3, u + 2);
        cp_commit();

        if (kit == 0) {
            #pragma unroll
            for (int mf = 0; mf < 4; mf++)
                #pragma unroll
                for (int nf = 0; nf < 4; nf++)
                    #pragma unroll
                    for (int q = 0; q < 4; q++) acc[mf][nf][q] = 0.f;
        }

        const uint32_t Bbase = sbase + P1_SM_B + (u % 3) * STAGEB;
        #pragma unroll
        for (int ks = 0; ks < 4; ks++) {
            uint32_t afr[4][4];
            #pragma unroll
            for (int mf = 0; mf < 4; mf++) {
                int rr  = warp_m * 64 + mf * 16 + ((g & 1) << 3) + r8;
                int c16 = kit * 8 + 2 * ks + (g >> 1);
                ldsm_x4(afr[mf][0], afr[mf][1], afr[mf][2], afr[mf][3],
                        sbase + P1_SM_A + SWA(rr, c16));
            }
            uint32_t bfr[2][4];
            #pragma unroll
            for (int nf2 = 0; nf2 < 2; nf2++) {
                int rr = warp_n * 32 + nf2 * 16 + ((g >> 1) << 3) + r8;
                int ch = 2 * ks + (g & 1);
                ldsm_x4(bfr[nf2][0], bfr[nf2][1], bfr[nf2][2], bfr[nf2][3],
                        Bbase + rr * 128 + ((ch ^ (rr & 7)) << 4));
            }
            #pragma unroll
            for (int mf = 0; mf < 4; mf++)
                #pragma unroll
                for (int nf = 0; nf < 4; nf++)
                    mma_bf16(acc[mf][nf], afr[mf],
                             bfr[nf >> 1][(nf & 1) * 2], bfr[nf >> 1][(nf & 1) * 2 + 1]);
        }

        if (kit == 7) {   // tile done: fold approx scores into top-2
            #pragma unroll
            for (int nf = 0; nf < 4; nf++) {
                const int code0 = nt * 128 + warp_n * 32 + nf * 8 + (lane & 3) * 2;
                const float c2a = __ldg(&g_c2[code0]);
                const float c2b = __ldg(&g_c2[code0 + 1]);
                #pragma unroll
                for (int mf = 0; mf < 4; mf++)
                    #pragma unroll
                    for (int h = 0; h < 2; h++) {
                        const int ridx = mf * 2 + h;
                        float v0 = c2a - 2.0f * acc[mf][nf][h * 2 + 0];
                        float v1 = c2b - 2.0f * acc[mf][nf][h * 2 + 1];
                        TOP2_UPD(v0, code0, ridx);
                        TOP2_UPD(v1, code0 + 1, ridx);
                    }
            }
        }
    }
    #undef P1_ISSUE
    #undef TOP2_UPD

    // per-row reduce: 16 slots x {v1, v2} -> gmin + candidates
    __syncthreads();
    float* rv = reinterpret_cast<float*>(sm + P1_SM_B);            // [128][32]
    int*   ri = reinterpret_cast<int*>(sm + P1_SM_B + 16384);      // [128][32]
    const int slot = warp_n * 4 + (lane & 3);
    #pragma unroll
    for (int ridx = 0; ridx < 8; ridx++) {
        const int rl = rowg[ridx] - row0;
        rv[rl * 32 + slot * 2 + 0] = tv1[ridx]; ri[rl * 32 + slot * 2 + 0] = ti1[ridx];
        rv[rl * 32 + slot * 2 + 1] = tv2[ridx]; ri[rl * 32 + slot * 2 + 1] = ti2[ridx];
    }
    __syncthreads();
    if (tid < 128) {
        float gmin = 3.4e38f;
        #pragma unroll
        for (int j = 0; j < 32; j++) gmin = fminf(gmin, rv[tid * 32 + j]);
        const float thr = gmin + MARGIN;
        int cnt = 0;
        #pragma unroll
        for (int j = 0; j < 32; j++) {
            if (rv[tid * 32 + j] < thr) {
                if (cnt < CCAP) g_cand[(row0 + tid) * CCAP + cnt] = ri[tid * 32 + j];
                cnt++;
            }
        }
        g_cand_cnt[row0 + tid] = cnt;
        g_gmin[row0 + tid]     = gmin;
    }
}

// ---------------------------------------------------------------------------
// Phase 2: rescore candidates exactly (fp64 dot, reference-grid fp32
// rounding, lowest-index tie-break). 1 warp per row.
// ---------------------------------------------------------------------------
__global__ __launch_bounds__(256) void phase2_kernel(const float* __restrict__ cb) {
    __shared__ int s_list[8][2 * CCAP];
    __shared__ int s_n[8];
    const int wid  = threadIdx.x >> 5;
    const int lane = threadIdx.x & 31;
    const int row  = blockIdx.x * 8 + wid;

    const int nc = g_cand_cnt[row];
    const int ns = g_spill_cnt[row];
    const float gmin = g_gmin[row];
    const bool fb = (nc > CCAP) || (ns > CCAP);

    const float* ze = g_ze + (size_t)row * D_;
    const float  zz = g_zz[row];
    float bv = 3.4e38f;
    int   bi = 0x7fffffff;

    if (!fb) {
        if (lane == 0) {
            int n = 0;
            for (int i = 0; i < nc; i++) s_list[wid][n++] = g_cand[row * CCAP + i];
            const float thr = gmin + MARGIN;
            for (int i = 0; i < ns; i++)
                if (g_spill_val[row * CCAP + i] < thr)
                    s_list[wid][n++] = g_spill_idx[row * CCAP + i];
            s_n[wid] = n;
        }
        __syncwarp();
        const int n = s_n[wid];
        for (int c = 0; c < n; c++) {
            const int k = s_list[wid][c];
            const float* cr = cb + (size_t)k * D_;
            double d = 0.0;
            #pragma unroll
            for (int j = 0; j < 16; j++) {
                int dd = lane + j * 32;
                d = fma((double)ze[dd], (double)cr[dd], d);
            }
            #pragma unroll
            for (int o = 16; o; o >>= 1) d += __shfl_xor_sync(0xffffffffu, d, o);
            float t = __fadd_rn(zz, -2.0f * (float)d);
            float v = __fadd_rn(t, g_c2[k]);
            if (v < bv || (v == bv && k < bi)) { bv = v; bi = k; }
        }
    } else {
        // pathological fallback: full exact scan of all K codes
        for (int k = 0; k < K_; k++) {
            const float* cr = cb + (size_t)k * D_;
            double d = 0.0;
            #pragma unroll
            for (int j = 0; j < 16; j++) {
                int dd = lane + j * 32;
                d = fma((double)ze[dd], (double)cr[dd], d);
            }
            #pragma unroll
            for (int o = 16; o; o >>= 1) d += __shfl_xor_sync(0xffffffffu, d, o);
            float t = __fadd_rn(zz, -2.0f * (float)d);
            float v = __fadd_rn(t, g_c2[k]);
            if (v < bv || (v == bv && k < bi)) { bv = v; bi = k; }
        }
    }
    if (lane == 0) g_idx[row] = bi;
}

// ---------------------------------------------------------------------------
// Output assembly
// ---------------------------------------------------------------------------
__global__ void output_kernel(const float* __restrict__ cb, float* __restrict__ out) {
    const int b   = blockIdx.x;
    const int tid = threadIdx.x;
    const int idx = g_idx[b];

    const float* ze = g_ze + (size_t)b * D_;
    const float* zq = cb   + (size_t)idx * D_;
    float*       o  = out  + (size_t)b * D_;

    float s = 0.f;
    #pragma unroll
    for (int d = tid; d < D_; d += 128) {
        float e    = ze[d];
        float q    = zq[d];
        float diff = q - e;
        o[d] = e + diff;
        s += diff * diff;
    }
    __shared__ float red[128];
    red[tid] = s;
    __syncthreads();
    #pragma unroll
    for (int o2 = 64; o2; o2 >>= 1) {
        if (tid < o2) red[tid] += red[tid + o2];
        __syncthreads();
    }
    if (tid == 0) {
        out[(size_t)B_ * D_ + b]      = (float)idx;
        out[(size_t)B_ * D_ + B_ + b] = red[0] / (float)D_;
    }
}

// ---------------------------------------------------------------------------
extern "C" void kernel_launch(void* const* d_in, const int* in_sizes, int n_in,
                              void* d_out, int out_size) {
    const float* x  = (const float*)d_in[0];
    const float* W  = (const float*)d_in[1];
    const float* cb = (const float*)d_in[2];
    float* out = (float*)d_out;
    (void)in_sizes; (void)n_in; (void)out_size;

    cudaFuncSetAttribute(gemm1_mma_kernel, cudaFuncAttributeMaxDynamicSharedMemorySize, SM1TOT);
    cudaFuncSetAttribute(phase1_kernel,    cudaFuncAttributeMaxDynamicSharedMemorySize, P1_SMTOT);

    pack_x_kernel<<<B_, 256>>>(x);
    pack_w_kernel<<<D_, 256>>>(W);
    c2_kernel<<<K_ / 8, 256>>>(cb);
    pack_cb_kernel<<<(int)(((size_t)K_ * D_) / 512), 256>>>(cb);
    gemm1_mma_kernel<<<dim3(4, 128), 256, SM1TOT>>>();
    zz_kernel<<<B_ / 8, 256>>>();
    pack_zb_kernel<<<(int)(((size_t)B_ * D_) / 512), 256>>>();
    phase1_kernel<<<128, 256, P1_SMTOT>>>();
    phase2_kernel<<<B_ / 8, 256>>>(cb);
    output_kernel<<<B_, 128>>>(cb, out);
}

// round 7
// speedup vs baseline: 1.4313x; 1.4313x over previous
#include <cuda_runtime.h>
#include <cuda_bf16.h>
#include <cuda_fp16.h>
#include <cstdint>

// Problem constants
#define B_   16384
#define DIN  1024
#define D_   512
#define K_   8192
#define KP2  3072          // gemm1 packed K: [a0|a0|a1] . [b0|b1|b0]

#define MARGIN2 0.08f      // collect margin incl. f16 quantization slack
#define CAP     32

// ---------------------------------------------------------------------------
// Scratch (device globals; allocations forbidden)
// ---------------------------------------------------------------------------
__device__ float  g_ze[(size_t)B_ * D_];     // z_e fp32
__device__ float  g_c2[K_];
__device__ float  g_zz[B_];
__device__ int    g_idx[B_];
__device__ float  g_pmin[8 * B_];            // per-(code-slice, row) partial min
__device__ __half g_dh[(size_t)B_ * K_];     // approx scores fp16, 256MB
__device__ __nv_bfloat16 g_xs[(size_t)B_ * KP2];   // packed x splits
__device__ __nv_bfloat16 g_ws[(size_t)D_ * KP2];   // packed W splits
__device__ __nv_bfloat16 g_zb[(size_t)B_ * D_];    // bf16(z_e)
__device__ __nv_bfloat16 g_cbb[(size_t)K_ * D_];   // bf16(cb)

// ---------------------------------------------------------------------------
// PTX helpers (baseline PTX only: works at .target sm_100)
// ---------------------------------------------------------------------------
__device__ __forceinline__ uint32_t smem_u32(const void* p) {
    uint32_t a;
    asm("{ .reg .u64 t; cvta.to.shared.u64 t, %1; cvt.u32.u64 %0, t; }" : "=r"(a) : "l"(p));
    return a;
}
__device__ __forceinline__ void cp_async16(uint32_t saddr, const void* gaddr) {
    asm volatile("cp.async.cg.shared.global [%0], [%1], 16;" :: "r"(saddr), "l"(gaddr));
}
__device__ __forceinline__ void cp_commit() { asm volatile("cp.async.commit_group;"); }
__device__ __forceinline__ void cp_wait1()  { asm volatile("cp.async.wait_group 1;" ::: "memory"); }

__device__ __forceinline__ void ldsm_x4(uint32_t& r0, uint32_t& r1, uint32_t& r2, uint32_t& r3,
                                        uint32_t addr) {
    asm volatile("ldmatrix.sync.aligned.m8n8.x4.shared.b16 {%0,%1,%2,%3}, [%4];"
                 : "=r"(r0), "=r"(r1), "=r"(r2), "=r"(r3) : "r"(addr));
}
__device__ __forceinline__ void mma_bf16(float* c, const uint32_t* a, uint32_t b0, uint32_t b1) {
    asm volatile("mma.sync.aligned.m16n8k16.row.col.f32.bf16.bf16.f32 "
                 "{%0,%1,%2,%3}, {%4,%5,%6,%7}, {%8,%9}, {%0,%1,%2,%3};"
                 : "+f"(c[0]), "+f"(c[1]), "+f"(c[2]), "+f"(c[3])
                 : "r"(a[0]), "r"(a[1]), "r"(a[2]), "r"(a[3]), "r"(b0), "r"(b1));
}

// A-resident swizzle for 512-col bf16 rows (64 x 16B chunks per row)
#define SWA(r, c) ((r) * 1024 + ((((c) & 0x38) | (((c) & 7) ^ ((r) & 7))) << 4))

// ---------------------------------------------------------------------------
// zz (needs g_ze; fp64 accumulation)
// ---------------------------------------------------------------------------
__global__ void zz_kernel() {
    int row  = blockIdx.x * 8 + (threadIdx.x >> 5);
    int lane = threadIdx.x & 31;
    const float* p = g_ze + (size_t)row * D_;
    double s = 0.0;
    #pragma unroll 4
    for (int i = lane; i < D_; i += 32) { double v = (double)p[i]; s += v * v; }
    #pragma unroll
    for (int o = 16; o; o >>= 1) s += __shfl_xor_sync(0xffffffffu, s, o);
    if (lane == 0) g_zz[row] = (float)s;
}

// ---------------------------------------------------------------------------
// Codebook prep: c2 + bf16 pack, single 16MB read. 1 warp per code row.
// ---------------------------------------------------------------------------
__global__ void cbprep_kernel(const float* __restrict__ cb) {
    const int row  = blockIdx.x * 8 + (threadIdx.x >> 5);
    const int lane = threadIdx.x & 31;
    const float4* src = reinterpret_cast<const float4*>(cb + (size_t)row * D_);
    __nv_bfloat162* dst = reinterpret_cast<__nv_bfloat162*>(g_cbb + (size_t)row * D_);
    float s = 0.f;
    #pragma unroll
    for (int j = 0; j < 4; j++) {
        const int i = lane + j * 32;
        float4 v = src[i];
        s += v.x * v.x + v.y * v.y + v.z * v.z + v.w * v.w;
        __nv_bfloat162 h0, h1;
        h0.x = __float2bfloat16_rn(v.x); h0.y = __float2bfloat16_rn(v.y);
        h1.x = __float2bfloat16_rn(v.z); h1.y = __float2bfloat16_rn(v.w);
        dst[i * 2]     = h0;
        dst[i * 2 + 1] = h1;
    }
    #pragma unroll
    for (int o = 16; o; o >>= 1) s += __shfl_xor_sync(0xffffffffu, s, o);
    if (lane == 0) g_c2[row] = s;
}

// ---------------------------------------------------------------------------
// Pack kernels for gemm1 operands
// ---------------------------------------------------------------------------
__global__ void pack_x_kernel(const float* __restrict__ x) {
    const int row = blockIdx.x, t = threadIdx.x;
    float4 v = *reinterpret_cast<const float4*>(x + (size_t)row * DIN + t * 4);
    __nv_bfloat162 h01, h23, l01, l23;
    h01.x = __float2bfloat16_rn(v.x); h01.y = __float2bfloat16_rn(v.y);
    h23.x = __float2bfloat16_rn(v.z); h23.y = __float2bfloat16_rn(v.w);
    l01.x = __float2bfloat16_rn(v.x - __bfloat162float(h01.x));
    l01.y = __float2bfloat16_rn(v.y - __bfloat162float(h01.y));
    l23.x = __float2bfloat16_rn(v.z - __bfloat162float(h23.x));
    l23.y = __float2bfloat16_rn(v.w - __bfloat162float(h23.y));
    __nv_bfloat162* d = reinterpret_cast<__nv_bfloat162*>(g_xs + (size_t)row * KP2 + t * 4);
    d[0] = h01; d[1] = h23;
    d += 512;  d[0] = h01; d[1] = h23;
    d += 512;  d[0] = l01; d[1] = l23;
}

__global__ void pack_w_kernel(const float* __restrict__ w) {
    const int row = blockIdx.x, t = threadIdx.x;
    float4 v = *reinterpret_cast<const float4*>(w + (size_t)row * DIN + t * 4);
    __nv_bfloat162 h01, h23, l01, l23;
    h01.x = __float2bfloat16_rn(v.x); h01.y = __float2bfloat16_rn(v.y);
    h23.x = __float2bfloat16_rn(v.z); h23.y = __float2bfloat16_rn(v.w);
    l01.x = __float2bfloat16_rn(v.x - __bfloat162float(h01.x));
    l01.y = __float2bfloat16_rn(v.y - __bfloat162float(h01.y));
    l23.x = __float2bfloat16_rn(v.z - __bfloat162float(h23.x));
    l23.y = __float2bfloat16_rn(v.w - __bfloat162float(h23.y));
    __nv_bfloat162* d = reinterpret_cast<__nv_bfloat162*>(g_ws + (size_t)row * KP2 + t * 4);
    d[0] = h01; d[1] = h23;
    d += 512;  d[0] = l01; d[1] = l23;
    d += 512;  d[0] = h01; d[1] = h23;
}

// ---------------------------------------------------------------------------
// GEMM1 via mma.sync: z_e = x @ W^T with packed 3-split (K''=3072).
// Epilogue also emits bf16(z_e) (replaces pack_zb kernel).
// ---------------------------------------------------------------------------
#define NS1    3
#define BLKK   64
#define STAGEB 16384
#define SM1_B  (NS1 * STAGEB)
#define SM1TOT (2 * NS1 * STAGEB)   // 96KB

__global__ __launch_bounds__(256, 1) void gemm1_mma_kernel() {
    extern __shared__ char sm[];
    const uint32_t sbase = smem_u32(sm);
    const int tid  = threadIdx.x;
    const int lane = tid & 31;
    const int wid  = tid >> 5;
    const int warp_m = wid & 1;
    const int warp_n = wid >> 1;
    const int row0 = blockIdx.y * 128;
    const int col0 = blockIdx.x * 128;
    const int NKIT = KP2 / BLKK;      // 48

    const __nv_bfloat16* gA = g_xs + (size_t)row0 * KP2;
    const __nv_bfloat16* gB = g_ws + (size_t)col0 * KP2;

    float acc[4][4][4];
    #pragma unroll
    for (int mf = 0; mf < 4; mf++)
        #pragma unroll
        for (int nf = 0; nf < 4; nf++)
            #pragma unroll
            for (int q = 0; q < 4; q++) acc[mf][nf][q] = 0.f;

    #define G1_ISSUE(stg, kit) do {                                                \
        const uint32_t As_ = sbase + (stg) * STAGEB;                               \
        const uint32_t Bs_ = sbase + SM1_B + (stg) * STAGEB;                       \
        const int koff_ = (kit) * BLKK;                                            \
        _Pragma("unroll")                                                          \
        for (int i_ = 0; i_ < 4; i_++) {                                           \
            int id_ = tid + i_ * 256;                                              \
            int r_  = id_ >> 3;                                                    \
            int c_  = id_ & 7;                                                     \
            int cp_ = c_ ^ (r_ & 7);                                               \
            cp_async16(As_ + r_ * 128 + cp_ * 16, gA + (size_t)r_ * KP2 + koff_ + c_ * 8); \
            cp_async16(Bs_ + r_ * 128 + cp_ * 16, gB + (size_t)r_ * KP2 + koff_ + c_ * 8); \
        }                                                                          \
    } while (0)

    G1_ISSUE(0, 0); cp_commit();
    G1_ISSUE(1, 1); cp_commit();

    const int g = lane >> 3;
    const int r8 = lane & 7;

    for (int kit = 0; kit < NKIT; kit++) {
        cp_wait1();
        __syncthreads();
        if (kit + 2 < NKIT) G1_ISSUE((kit + 2) % NS1, kit + 2);
        cp_commit();

        const int stg = kit % NS1;
        const uint32_t Abase = sbase + stg * STAGEB;
        const uint32_t Bbase = sbase + SM1_B + stg * STAGEB;

        #pragma unroll
        for (int ks = 0; ks < 4; ks++) {
            uint32_t afr[4][4];
            #pragma unroll
            for (int mf = 0; mf < 4; mf++) {
                int rr = warp_m * 64 + mf * 16 + ((g & 1) << 3) + r8;
                int ch = 2 * ks + (g >> 1);
                ldsm_x4(afr[mf][0], afr[mf][1], afr[mf][2], afr[mf][3],
                        Abase + rr * 128 + ((ch ^ (rr & 7)) << 4));
            }
            uint32_t bfr[2][4];
            #pragma unroll
            for (int nf2 = 0; nf2 < 2; nf2++) {
                int rr = warp_n * 32 + nf2 * 16 + ((g >> 1) << 3) + r8;
                int ch = 2 * ks + (g & 1);
                ldsm_x4(bfr[nf2][0], bfr[nf2][1], bfr[nf2][2], bfr[nf2][3],
                        Bbase + rr * 128 + ((ch ^ (rr & 7)) << 4));
            }
            #pragma unroll
            for (int mf = 0; mf < 4; mf++)
                #pragma unroll
                for (int nf = 0; nf < 4; nf++)
                    mma_bf16(acc[mf][nf], afr[mf],
                             bfr[nf >> 1][(nf & 1) * 2], bfr[nf >> 1][(nf & 1) * 2 + 1]);
        }
    }
    #undef G1_ISSUE

    #pragma unroll
    for (int mf = 0; mf < 4; mf++)
        #pragma unroll
        for (int h = 0; h < 2; h++) {
            const int row = row0 + warp_m * 64 + mf * 16 + h * 8 + (lane >> 2);
            #pragma unroll
            for (int nf = 0; nf < 4; nf++) {
                const int col = col0 + warp_n * 32 + nf * 8 + (lane & 3) * 2;
                float2 o; o.x = acc[mf][nf][h * 2]; o.y = acc[mf][nf][h * 2 + 1];
                *reinterpret_cast<float2*>(g_ze + (size_t)row * D_ + col) = o;
                __nv_bfloat162 hb;
                hb.x = __float2bfloat16_rn(o.x); hb.y = __float2bfloat16_rn(o.y);
                *reinterpret_cast<__nv_bfloat162*>(g_zb + (size_t)row * D_ + col) = hb;
            }
        }
}

// ---------------------------------------------------------------------------
// Phase 1: single-pass bf16 approx GEMM. Stores fp16 scores s = c2 - 2*dot
// to g_dh AND folds a branchless per-thread running min, block-reduced to
// g_pmin[bx][row]. A resident (128KB swizzled), B streamed 3-stage.
// grid (8, 128).
// ---------------------------------------------------------------------------
#define P1_SM_A  0
#define P1_SM_B  131072
#define P1_SMTOT (131072 + 3 * STAGEB)   // 180224

__global__ __launch_bounds__(256, 1) void phase1_kernel() {
    extern __shared__ char sm[];
    const uint32_t sbase = smem_u32(sm);
    const int tid  = threadIdx.x;
    const int lane = tid & 31;
    const int wid  = tid >> 5;
    const int warp_m = wid & 1;
    const int warp_n = wid >> 1;
    const int row0 = blockIdx.y * 128;
    const int code_base = blockIdx.x * 1024;

    // resident A: 128 rows x 64 chunks(16B)
    {
        const __nv_bfloat16* gA = g_zb + (size_t)row0 * D_;
        #pragma unroll
        for (int i = 0; i < 32; i++) {
            int idx = tid + i * 256;
            int r   = idx >> 6;
            int c16 = idx & 63;
            cp_async16(sbase + P1_SM_A + SWA(r, c16), gA + (size_t)r * D_ + c16 * 8);
        }
    }
    cp_commit();

    #define P1_ISSUE(stg, u) do {                                                  \
        const uint32_t Bs_ = sbase + P1_SM_B + (stg) * STAGEB;                     \
        const int nt_ = (u) >> 3, kit_ = (u) & 7;                                  \
        const __nv_bfloat16* gB_ = g_cbb + (size_t)(code_base + nt_ * 128) * D_;   \
        _Pragma("unroll")                                                          \
        for (int i_ = 0; i_ < 4; i_++) {                                           \
            int id_ = tid + i_ * 256;                                              \
            int r_  = id_ >> 3;                                                    \
            int c_  = id_ & 7;                                                     \
            cp_async16(Bs_ + r_ * 128 + ((c_ ^ (r_ & 7)) << 4),                    \
                       gB_ + (size_t)r_ * D_ + kit_ * BLKK + c_ * 8);              \
        }                                                                          \
    } while (0)

    P1_ISSUE(0, 0); cp_commit();
    P1_ISSUE(1, 1); cp_commit();

    const int g = lane >> 3;
    const int r8 = lane & 7;
    float acc[4][4][4];
    float rmin[8];
    #pragma unroll
    for (int i = 0; i < 8; i++) rmin[i] = 3.4e38f;

    for (int u = 0; u < 64; u++) {
        const int nt = u >> 3, kit = u & 7;
        cp_wait1();
        __syncthreads();
        if (u + 2 < 64) P1_ISSUE((u + 2) % 3, u + 2);
        cp_commit();

        if (kit == 0) {
            #pragma unroll
            for (int mf = 0; mf < 4; mf++)
                #pragma unroll
                for (int nf = 0; nf < 4; nf++)
                    #pragma unroll
                    for (int q = 0; q < 4; q++) acc[mf][nf][q] = 0.f;
        }

        const uint32_t Bbase = sbase + P1_SM_B + (u % 3) * STAGEB;
        #pragma unroll
        for (int ks = 0; ks < 4; ks++) {
            uint32_t afr[4][4];
            #pragma unroll
            for (int mf = 0; mf < 4; mf++) {
                int rr  = warp_m * 64 + mf * 16 + ((g & 1) << 3) + r8;
                int c16 = kit * 8 + 2 * ks + (g >> 1);
                ldsm_x4(afr[mf][0], afr[mf][1], afr[mf][2], afr[mf][3],
                        sbase + P1_SM_A + SWA(rr, c16));
            }
            uint32_t bfr[2][4];
            #pragma unroll
            for (int nf2 = 0; nf2 < 2; nf2++) {
                int rr = warp_n * 32 + nf2 * 16 + ((g >> 1) << 3) + r8;
                int ch = 2 * ks + (g & 1);
                ldsm_x4(bfr[nf2][0], bfr[nf2][1], bfr[nf2][2], bfr[nf2][3],
                        Bbase + rr * 128 + ((ch ^ (rr & 7)) << 4));
            }
            #pragma unroll
            for (int mf = 0; mf < 4; mf++)
                #pragma unroll
                for (int nf = 0; nf < 4; nf++)
                    mma_bf16(acc[mf][nf], afr[mf],
                             bfr[nf >> 1][(nf & 1) * 2], bfr[nf >> 1][(nf & 1) * 2 + 1]);
        }

        if (kit == 7) {   // tile done: store f16 scores + fold min (branchless)
            #pragma unroll
            for (int nf = 0; nf < 4; nf++) {
                const int code0 = code_base + nt * 128 + warp_n * 32 + nf * 8 + (lane & 3) * 2;
                const float c2a = __ldg(&g_c2[code0]);
                const float c2b = __ldg(&g_c2[code0 + 1]);
                #pragma unroll
                for (int mf = 0; mf < 4; mf++)
                    #pragma unroll
                    for (int h = 0; h < 2; h++) {
                        const int ridx = mf * 2 + h;
                        const int row = row0 + warp_m * 64 + mf * 16 + h * 8 + (lane >> 2);
                        float v0 = c2a - 2.0f * acc[mf][nf][h * 2 + 0];
                        float v1 = c2b - 2.0f * acc[mf][nf][h * 2 + 1];
                        rmin[ridx] = fminf(rmin[ridx], fminf(v0, v1));
                        *reinterpret_cast<__half2*>(g_dh + (size_t)row * K_ + code0) =
                            __floats2half2_rn(v0, v1);
                    }
            }
        }
    }
    #undef P1_ISSUE

    // block reduce per-row mins (16 owners per row) -> g_pmin[bx][row]
    __syncthreads();
    float* rv = reinterpret_cast<float*>(sm + P1_SM_B);   // [128][16]
    const int slot = warp_n * 4 + (lane & 3);
    #pragma unroll
    for (int ridx = 0; ridx < 8; ridx++) {
        const int mf = ridx >> 1, h = ridx & 1;
        const int rl = warp_m * 64 + mf * 16 + h * 8 + (lane >> 2);
        rv[rl * 16 + slot] = rmin[ridx];
    }
    __syncthreads();
    if (tid < 128) {
        float m = rv[tid * 16];
        #pragma unroll
        for (int j = 1; j < 16; j++) m = fminf(m, rv[tid * 16 + j]);
        g_pmin[blockIdx.x * B_ + row0 + tid] = m;
    }
}

// ---------------------------------------------------------------------------
// Phase 2: gmin from g_pmin, ONE sweep of fp16 scores to collect candidates,
// exact fp64 rescore with reference-grid fp32 rounding + index tie-break.
// 1 warp per row.
// ---------------------------------------------------------------------------
__global__ __launch_bounds__(256) void phase2_kernel(const float* __restrict__ cb) {
    __shared__ int s_cnt[8];
    __shared__ int s_list[8][CAP];
    const int wid  = threadIdx.x >> 5;
    const int lane = threadIdx.x & 31;
    const int row  = blockIdx.x * 8 + wid;

    // global min across 8 code-slices
    float gmin = 3.4e38f;
    if (lane < 8) gmin = g_pmin[lane * B_ + row];
    #pragma unroll
    for (int o = 4; o; o >>= 1) gmin = fminf(gmin, __shfl_xor_sync(0xffffffffu, gmin, o));
    gmin = __shfl_sync(0xffffffffu, gmin, 0);
    const float thr = gmin + MARGIN2;

    if (lane == 0) s_cnt[wid] = 0;
    __syncwarp();

    // single sweep: 8192 fp16 scores per row = 32 uint4 per lane
    const uint4* dp = reinterpret_cast<const uint4*>(g_dh + (size_t)row * K_);
    #pragma unroll 4
    for (int i = 0; i < 32; i++) {
        uint4 v = dp[lane + i * 32];
        const int k0 = (lane + i * 32) * 8;
        const uint32_t w[4] = { v.x, v.y, v.z, v.w };
        #pragma unroll
        for (int q = 0; q < 4; q++) {
            __half2 h = *reinterpret_cast<const __half2*>(&w[q]);
            float2 f = __half22float2(h);
            if (f.x < thr) { int p = atomicAdd(&s_cnt[wid], 1); if (p < CAP) s_list[wid][p] = k0 + q * 2; }
            if (f.y < thr) { int p = atomicAdd(&s_cnt[wid], 1); if (p < CAP) s_list[wid][p] = k0 + q * 2 + 1; }
        }
    }
    __syncwarp();
    const int ncand = s_cnt[wid];

    const float* ze = g_ze + (size_t)row * D_;
    const float  zz = g_zz[row];
    float bv = 3.4e38f;
    int   bi = 0x7fffffff;

    if (ncand <= CAP) {
        for (int c = 0; c < ncand; c++) {
            const int k = s_list[wid][c];
            const float* cr = cb + (size_t)k * D_;
            double d = 0.0;
            #pragma unroll
            for (int j = 0; j < 16; j++) {
                int dd = lane + j * 32;
                d = fma((double)ze[dd], (double)cr[dd], d);
            }
            #pragma unroll
            for (int o = 16; o; o >>= 1) d += __shfl_xor_sync(0xffffffffu, d, o);
            float t = __fadd_rn(zz, -2.0f * (float)d);
            float v = __fadd_rn(t, g_c2[k]);
            if (v < bv || (v == bv && k < bi)) { bv = v; bi = k; }
        }
    } else {
        // pathological fallback: full exact scan
        for (int k = 0; k < K_; k++) {
            const float* cr = cb + (size_t)k * D_;
            double d = 0.0;
            #pragma unroll
            for (int j = 0; j < 16; j++) {
                int dd = lane + j * 32;
                d = fma((double)ze[dd], (double)cr[dd], d);
            }
            #pragma unroll
            for (int o = 16; o; o >>= 1) d += __shfl_xor_sync(0xffffffffu, d, o);
            float t = __fadd_rn(zz, -2.0f * (float)d);
            float v = __fadd_rn(t, g_c2[k]);
            if (v < bv || (v == bv && k < bi)) { bv = v; bi = k; }
        }
    }
    if (lane == 0) g_idx[row] = bi;
}

// ---------------------------------------------------------------------------
// Output assembly
// ---------------------------------------------------------------------------
__global__ void output_kernel(const float* __restrict__ cb, float* __restrict__ out) {
    const int b   = blockIdx.x;
    const int tid = threadIdx.x;
    const int idx = g_idx[b];

    const float* ze = g_ze + (size_t)b * D_;
    const float* zq = cb   + (size_t)idx * D_;
    float*       o  = out  + (size_t)b * D_;

    float s = 0.f;
    #pragma unroll
    for (int d = tid; d < D_; d += 128) {
        float e    = ze[d];
        float q    = zq[d];
        float diff = q - e;
        o[d] = e + diff;
        s += diff * diff;
    }
    __shared__ float red[128];
    red[tid] = s;
    __syncthreads();
    #pragma unroll
    for (int o2 = 64; o2; o2 >>= 1) {
        if (tid < o2) red[tid] += red[tid + o2];
        __syncthreads();
    }
    if (tid == 0) {
        out[(size_t)B_ * D_ + b]      = (float)idx;
        out[(size_t)B_ * D_ + B_ + b] = red[0] / (float)D_;
    }
}

// ---------------------------------------------------------------------------
extern "C" void kernel_launch(void* const* d_in, const int* in_sizes, int n_in,
                              void* d_out, int out_size) {
    const float* x  = (const float*)d_in[0];
    const float* W  = (const float*)d_in[1];
    const float* cb = (const float*)d_in[2];
    float* out = (float*)d_out;
    (void)in_sizes; (void)n_in; (void)out_size;

    cudaFuncSetAttribute(gemm1_mma_kernel, cudaFuncAttributeMaxDynamicSharedMemorySize, SM1TOT);
    cudaFuncSetAttribute(phase1_kernel,    cudaFuncAttributeMaxDynamicSharedMemorySize, P1_SMTOT);

    pack_x_kernel<<<B_, 256>>>(x);
    pack_w_kernel<<<D_, 256>>>(W);
    cbprep_kernel<<<K_ / 8, 256>>>(cb);
    gemm1_mma_kernel<<<dim3(4, 128), 256, SM1TOT>>>();
    zz_kernel<<<B_ / 8, 256>>>();
    phase1_kernel<<<dim3(8, 128), 256, P1_SMTOT>>>();
    phase2_kernel<<<B_ / 8, 256>>>(cb);
    output_kernel<<<B_, 128>>>(cb, out);
}